// round 7
// baseline (speedup 1.0000x reference)
#include <cuda_runtime.h>
#include <math.h>

#define Bb   2
#define Tt   2048
#define Dd   2048
#define Hh   16
#define KVh  4
#define HDd  128
#define REP  (Hh / KVh)
#define NROW (Bb * Tt)
#define QW   (Hh * HDd)    // 2048
#define KW   (KVh * HDd)   // 512

// ---- scratch (static device globals; no allocation) ----
__device__ float g_Q[(size_t)NROW * QW];
__device__ float g_K[(size_t)NROW * KW];
__device__ float g_V[(size_t)NROW * KW];
__device__ float g_O[(size_t)NROW * QW];
__device__ float g_cos[Tt * (HDd / 2)];
__device__ float g_sin[Tt * (HDd / 2)];

// ============================================================
// common PTX helpers
// ============================================================
__device__ __forceinline__ unsigned f2tf32(float x) {
    unsigned r;
    asm("cvt.rna.tf32.f32 %0, %1;" : "=r"(r) : "f"(x));
    return r;
}

__device__ __forceinline__ void ldm_x4(unsigned* a, const unsigned* p) {
    unsigned addr = (unsigned)__cvta_generic_to_shared(p);
    asm volatile("ldmatrix.sync.aligned.m8n8.x4.shared.b16 {%0,%1,%2,%3}, [%4];"
        : "=r"(a[0]), "=r"(a[1]), "=r"(a[2]), "=r"(a[3]) : "r"(addr));
}

__device__ __forceinline__ void mma_tf32(float* c, const unsigned* a,
                                         unsigned b0, unsigned b1) {
    asm volatile(
        "mma.sync.aligned.m16n8k8.row.col.f32.tf32.tf32.f32 "
        "{%0,%1,%2,%3}, {%4,%5,%6,%7}, {%8,%9}, {%0,%1,%2,%3};"
        : "+f"(c[0]), "+f"(c[1]), "+f"(c[2]), "+f"(c[3])
        : "r"(a[0]), "r"(a[1]), "r"(a[2]), "r"(a[3]), "r"(b0), "r"(b1));
}

// ============================================================
// RoPE tables (double precision)
// ============================================================
__global__ void rope_tables_kernel() {
    int idx = blockIdx.x * blockDim.x + threadIdx.x;
    if (idx >= Tt * (HDd / 2)) return;
    int i = idx % (HDd / 2);
    int t = idx / (HDd / 2);
    double inv = exp(-((double)(2 * i) / (double)HDd) * log(10000.0));
    double a = (double)t * inv;
    g_cos[idx] = (float)cos(a);
    g_sin[idx] = (float)sin(a);
}

// ============================================================
// TF32 tensor-core GEMM with optional dual-output region and
// fused-RoPE epilogue. (unchanged from round 6)
// ============================================================
#define BM 128
#define BN 128
#define BK 32
#define LDA 36
#define LDB 132
#define ASZ (BM * LDA)
#define BSZ (BK * LDB)
#define SMEM_GEMM ((2 * ASZ + 2 * BSZ) * 4)

__global__ __launch_bounds__(256, 2) void gemm_tf32_kernel(
    const float* __restrict__ A,
    const float* __restrict__ B0, const float* __restrict__ B1,
    float* __restrict__ C0, float* __restrict__ C1,
    int split_bx, int rope_bx, int N, int K)
{
    extern __shared__ unsigned smem_u[];
    unsigned* As = smem_u;
    unsigned* Bs = smem_u + 2 * ASZ;

    const int bxr = blockIdx.x, by = blockIdx.y;
    const float* Bm;
    float* C;
    int bx;
    if (bxr < split_bx) { Bm = B0; C = C0; bx = bxr; }
    else                { Bm = B1; C = C1; bx = bxr - split_bx; }
    const bool rope = (bxr < rope_bx);

    const int tid = threadIdx.x;
    const int warp = tid >> 5, lane = tid & 31;
    const int wm = warp & 3;
    const int wn = warp >> 2;

    const int ar = tid >> 3;
    const int ac = (tid & 7) << 2;
    const int br = tid >> 5;
    const int bc = (tid & 31) << 2;

    const float* Ag = A + (size_t)(by * BM) * K;
    const float* Bg = Bm + bx * BN;

    float acc[2][8][4];
#pragma unroll
    for (int mt = 0; mt < 2; mt++)
#pragma unroll
        for (int nt = 0; nt < 8; nt++)
#pragma unroll
            for (int i = 0; i < 4; i++) acc[mt][nt][i] = 0.f;

    float4 av[4], bv[4];

#pragma unroll
    for (int i = 0; i < 4; i++)
        av[i] = *(const float4*)(Ag + (size_t)(ar + 32 * i) * K + ac);
#pragma unroll
    for (int i = 0; i < 4; i++)
        bv[i] = *(const float4*)(Bg + (size_t)(br + 8 * i) * N + bc);
#pragma unroll
    for (int i = 0; i < 4; i++) {
        uint4 u;
        u.x = f2tf32(av[i].x); u.y = f2tf32(av[i].y);
        u.z = f2tf32(av[i].z); u.w = f2tf32(av[i].w);
        *(uint4*)&As[(ar + 32 * i) * LDA + ac] = u;
        uint4 w;
        w.x = f2tf32(bv[i].x); w.y = f2tf32(bv[i].y);
        w.z = f2tf32(bv[i].z); w.w = f2tf32(bv[i].w);
        *(uint4*)&Bs[(br + 8 * i) * LDB + bc] = w;
    }
    __syncthreads();

    int buf = 0;
    for (int k0 = BK; k0 <= K; k0 += BK) {
        if (k0 < K) {
#pragma unroll
            for (int i = 0; i < 4; i++)
                av[i] = *(const float4*)(Ag + (size_t)(ar + 32 * i) * K + k0 + ac);
#pragma unroll
            for (int i = 0; i < 4; i++)
                bv[i] = *(const float4*)(Bg + (size_t)(k0 + br + 8 * i) * N + bc);
        }

        const unsigned* Ab = As + buf * ASZ;
        const unsigned* Bt = Bs + buf * BSZ;
        const int arow = (lane & 7) + ((lane >> 3) & 1) * 8;
        const int acol = (lane >> 4) << 2;
#pragma unroll
        for (int ks = 0; ks < 4; ks++) {
            unsigned afr[2][4];
#pragma unroll
            for (int mt = 0; mt < 2; mt++) {
                int m0 = wm * 32 + mt * 16;
                ldm_x4(afr[mt], Ab + (m0 + arow) * LDA + ks * 8 + acol);
            }
            const unsigned* Bk = Bt + (ks * 8 + (lane & 3)) * LDB + wn * 64 + (lane >> 2);
#pragma unroll
            for (int nt = 0; nt < 8; nt++) {
                unsigned b0 = Bk[nt * 8];
                unsigned b1 = Bk[nt * 8 + 4 * LDB];
                mma_tf32(acc[0][nt], afr[0], b0, b1);
                mma_tf32(acc[1][nt], afr[1], b0, b1);
            }
        }

        if (k0 < K) {
            unsigned* Aw = As + (buf ^ 1) * ASZ;
            unsigned* Bw = Bs + (buf ^ 1) * BSZ;
#pragma unroll
            for (int i = 0; i < 4; i++) {
                uint4 u;
                u.x = f2tf32(av[i].x); u.y = f2tf32(av[i].y);
                u.z = f2tf32(av[i].z); u.w = f2tf32(av[i].w);
                *(uint4*)&Aw[(ar + 32 * i) * LDA + ac] = u;
                uint4 w;
                w.x = f2tf32(bv[i].x); w.y = f2tf32(bv[i].y);
                w.z = f2tf32(bv[i].z); w.w = f2tf32(bv[i].w);
                *(uint4*)&Bw[(br + 8 * i) * LDB + bc] = w;
            }
            __syncthreads();
            buf ^= 1;
        }
    }

    // ---- epilogue (optional fused RoPE) ----
    const int g = lane >> 2;
    const int cc = (lane & 3) << 1;
#pragma unroll
    for (int mt = 0; mt < 2; mt++) {
#pragma unroll
        for (int nt = 0; nt < 8; nt++) {
            int row = by * BM + wm * 32 + mt * 16 + g;
            int col = bx * BN + wn * 64 + nt * 8 + cc;
            if (rope) {
                int i = (col & (HDd - 1)) >> 1;
                int t0 = row & (Tt - 1);
                float c0 = g_cos[t0 * 64 + i], s0 = g_sin[t0 * 64 + i];
                float x1 = acc[mt][nt][0], x2 = acc[mt][nt][1];
                acc[mt][nt][0] = x1 * c0 - x2 * s0;
                acc[mt][nt][1] = x1 * s0 + x2 * c0;
                int t1 = (row + 8) & (Tt - 1);
                float c1 = g_cos[t1 * 64 + i], s1 = g_sin[t1 * 64 + i];
                x1 = acc[mt][nt][2]; x2 = acc[mt][nt][3];
                acc[mt][nt][2] = x1 * c1 - x2 * s1;
                acc[mt][nt][3] = x1 * s1 + x2 * c1;
            }
            *(float2*)&C[(size_t)row * N + col] =
                make_float2(acc[mt][nt][0], acc[mt][nt][1]);
            *(float2*)&C[(size_t)(row + 8) * N + col] =
                make_float2(acc[mt][nt][2], acc[mt][nt][3]);
        }
    }
}

// ============================================================
// TF32 tensor-core flash attention, causal, GQA.
// 128 threads = 4 warps; Q tile 64 rows (16/warp), KV tile 64.
// QK^T B-fragments via ldmatrix on K[j][d].
// PV  B-fragments via ldmatrix on swizzled V^T[d][j]  (NEW).
// smem: Qs[64][132] | union( K[64][132] , Vt[128][68] swizzled ) | Ps[64][68]
// ============================================================
#define LDQ 132
#define LDK 132
#define LDVT 68
#define LDP 68
#define UNION_SZ (HDd * LDVT)                 // 8704 words >= 64*LDK=8448
#define SMEM_ATTN ((64 * LDQ + UNION_SZ + 64 * LDP) * 4)   // 86016 B

__global__ __launch_bounds__(128) void attn_mma_kernel() {
    extern __shared__ unsigned smu[];
    unsigned* Qs = smu;
    unsigned* KV = Qs + 64 * LDQ;     // K tile OR transposed V tile
    unsigned* Ps = KV + UNION_SZ;

    const int bh = blockIdx.y;
    const int b = bh / Hh;
    const int h = bh % Hh;
    const int kvh = h / REP;
    const int q0 = blockIdx.x * 64;
    const int tid = threadIdx.x, warp = tid >> 5, lane = tid & 31;
    const int g = lane >> 2, qd = lane & 3;
    const int arow = (lane & 7) + ((lane >> 3) & 1) * 8;
    const int acol = (lane >> 4) << 2;
    const float scale = 0.08838834764831845f; // 1/sqrt(128)

    // load Q tile (scale folded in, converted to tf32)
    const float* Qg = g_Q + ((size_t)(b * Tt + q0)) * QW + h * HDd;
    for (int x = tid; x < 64 * 32; x += 128) {
        int r = x >> 5, d4 = (x & 31) << 2;
        float4 q = *(const float4*)(Qg + (size_t)r * QW + d4);
        Qs[r * LDQ + d4 + 0] = f2tf32(q.x * scale);
        Qs[r * LDQ + d4 + 1] = f2tf32(q.y * scale);
        Qs[r * LDQ + d4 + 2] = f2tf32(q.z * scale);
        Qs[r * LDQ + d4 + 3] = f2tf32(q.w * scale);
    }

    float o[16][4];
#pragma unroll
    for (int nt = 0; nt < 16; nt++)
#pragma unroll
        for (int i = 0; i < 4; i++) o[nt][i] = 0.f;
    float m0 = -1e30f, m1 = -1e30f, l0 = 0.f, l1 = 0.f;

    // V^T store mapping: warp owns d in [warp*32, warp*32+32)
    const int vt_d0 = warp * 32 + (lane & 7) * 4;   // d base (mult of 4)
    const int vt_jl = lane >> 3;                    // 0..3
    const unsigned vt_swz_d = (unsigned)((vt_d0 >> 2) & 7);

    const int ntiles = blockIdx.x + 1;
    for (int tile = 0; tile < ntiles; tile++) {
        const int j0 = tile * 64;
        __syncthreads();   // prev V^T reads done (and Q stores on iter 0)

        // load K tile -> KV (row-major [j][d], tf32)
        const float* Kg = g_K + ((size_t)(b * Tt + j0)) * KW + kvh * HDd;
        for (int x = tid; x < 64 * 32; x += 128) {
            int j = x >> 5, d4 = (x & 31) << 2;
            float4 kv = *(const float4*)(Kg + (size_t)j * KW + d4);
            KV[j * LDK + d4 + 0] = f2tf32(kv.x);
            KV[j * LDK + d4 + 1] = f2tf32(kv.y);
            KV[j * LDK + d4 + 2] = f2tf32(kv.z);
            KV[j * LDK + d4 + 3] = f2tf32(kv.w);
        }
        __syncthreads();

        // ---- S = (Q*scale) @ K^T : warp rows warp*16..+16, cols 0..63 ----
        float s[8][4];
#pragma unroll
        for (int nt = 0; nt < 8; nt++)
#pragma unroll
            for (int i = 0; i < 4; i++) s[nt][i] = 0.f;

#pragma unroll
        for (int ks = 0; ks < 16; ks++) {
            unsigned afr[4];
            ldm_x4(afr, Qs + (warp * 16 + arow) * LDQ + ks * 8 + acol);
#pragma unroll
            for (int ntp = 0; ntp < 4; ntp++) {
                unsigned bfr[4];
                ldm_x4(bfr, KV + (ntp * 16 + arow) * LDK + ks * 8 + acol);
                mma_tf32(s[2 * ntp],     afr, bfr[0], bfr[2]);
                mma_tf32(s[2 * ntp + 1], afr, bfr[1], bfr[3]);
            }
        }

        // causal mask on diagonal tile
        if (j0 == q0) {
            int r0 = warp * 16 + g, r1 = r0 + 8;
#pragma unroll
            for (int nt = 0; nt < 8; nt++) {
                int c = nt * 8 + 2 * qd;
                if (c > r0)     s[nt][0] = -1e30f;
                if (c + 1 > r0) s[nt][1] = -1e30f;
                if (c > r1)     s[nt][2] = -1e30f;
                if (c + 1 > r1) s[nt][3] = -1e30f;
            }
        }

        // ---- online softmax ----
        float mx0 = -1e30f, mx1 = -1e30f;
#pragma unroll
        for (int nt = 0; nt < 8; nt++) {
            mx0 = fmaxf(mx0, fmaxf(s[nt][0], s[nt][1]));
            mx1 = fmaxf(mx1, fmaxf(s[nt][2], s[nt][3]));
        }
        mx0 = fmaxf(mx0, __shfl_xor_sync(0xFFFFFFFFu, mx0, 1));
        mx0 = fmaxf(mx0, __shfl_xor_sync(0xFFFFFFFFu, mx0, 2));
        mx1 = fmaxf(mx1, __shfl_xor_sync(0xFFFFFFFFu, mx1, 1));
        mx1 = fmaxf(mx1, __shfl_xor_sync(0xFFFFFFFFu, mx1, 2));

        float mn0 = fmaxf(m0, mx0), mn1 = fmaxf(m1, mx1);
        float a0 = __expf(m0 - mn0), a1 = __expf(m1 - mn1);
        m0 = mn0; m1 = mn1;

        float ps0 = 0.f, ps1 = 0.f;
        unsigned* Pr0 = Ps + (warp * 16 + g) * LDP;
        unsigned* Pr1 = Pr0 + 8 * LDP;
#pragma unroll
        for (int nt = 0; nt < 8; nt++) {
            float p0 = __expf(s[nt][0] - mn0);
            float p1 = __expf(s[nt][1] - mn0);
            float p2 = __expf(s[nt][2] - mn1);
            float p3 = __expf(s[nt][3] - mn1);
            ps0 += p0 + p1; ps1 += p2 + p3;
            int c = nt * 8 + 2 * qd;
            *(uint2*)&Pr0[c] = make_uint2(f2tf32(p0), f2tf32(p1));
            *(uint2*)&Pr1[c] = make_uint2(f2tf32(p2), f2tf32(p3));
        }
        ps0 += __shfl_xor_sync(0xFFFFFFFFu, ps0, 1);
        ps0 += __shfl_xor_sync(0xFFFFFFFFu, ps0, 2);
        ps1 += __shfl_xor_sync(0xFFFFFFFFu, ps1, 1);
        ps1 += __shfl_xor_sync(0xFFFFFFFFu, ps1, 2);
        l0 = l0 * a0 + ps0;
        l1 = l1 * a1 + ps1;
#pragma unroll
        for (int nt = 0; nt < 16; nt++) {
            o[nt][0] *= a0; o[nt][1] *= a0;
            o[nt][2] *= a1; o[nt][3] *= a1;
        }

        __syncthreads();  // all warps done reading K

        // load V tile -> KV as transposed Vt[d][j], XOR-swizzled, tf32.
        // Vt addr(d, j) = d*LDVT + ((j>>2) ^ ((d>>2)&7))*4 + (j&3)
        // Store pattern is conflict-free (banks 4*(it^dl4)+jl cover all 32).
        {
            const float* Vg = g_V + ((size_t)(b * Tt + j0)) * KW + kvh * HDd;
#pragma unroll
            for (int it = 0; it < 16; it++) {
                int j = it * 4 + vt_jl;
                float4 vv = *(const float4*)(Vg + (size_t)j * KW + vt_d0);
                unsigned base = (unsigned)vt_d0 * LDVT
                              + (((unsigned)it ^ vt_swz_d) << 2) + vt_jl;
                KV[base]            = f2tf32(vv.x);
                KV[base + LDVT]     = f2tf32(vv.y);
                KV[base + 2 * LDVT] = f2tf32(vv.z);
                KV[base + 3 * LDVT] = f2tf32(vv.w);
            }
        }
        __syncthreads();

        // ---- O += P @ V : B-fragments via ldmatrix on swizzled Vt ----
#pragma unroll
        for (int ks = 0; ks < 8; ks++) {
            unsigned afr[4];
            ldm_x4(afr, Ps + (warp * 16 + arow) * LDP + ks * 8 + acol);
#pragma unroll
            for (int ntp = 0; ntp < 8; ntp++) {
                int row = ntp * 16 + arow;
                unsigned chunk = (unsigned)(ks * 2 + (lane >> 4));
                unsigned swz = (chunk ^ ((unsigned)(row >> 2) & 7)) << 2;
                unsigned bfr[4];
                ldm_x4(bfr, KV + row * LDVT + swz);
                mma_tf32(o[2 * ntp],     afr, bfr[0], bfr[2]);
                mma_tf32(o[2 * ntp + 1], afr, bfr[1], bfr[3]);
            }
        }
    }

    // ---- epilogue: normalize, store ----
    float i0 = 1.f / l0, i1 = 1.f / l1;
    float* Og = g_O + ((size_t)(b * Tt + q0 + warp * 16 + g)) * QW + h * HDd;
#pragma unroll
    for (int nt = 0; nt < 16; nt++) {
        int c = nt * 8 + 2 * qd;
        *(float2*)(Og + c) = make_float2(o[nt][0] * i0, o[nt][1] * i0);
        *(float2*)(Og + (size_t)8 * QW + c) = make_float2(o[nt][2] * i1, o[nt][3] * i1);
    }
}

// ============================================================
extern "C" void kernel_launch(void* const* d_in, const int* in_sizes, int n_in,
                              void* d_out, int out_size) {
    (void)in_sizes; (void)n_in; (void)out_size;
    const float* x  = (const float*)d_in[0];
    const float* Wq = (const float*)d_in[1];
    const float* Wk = (const float*)d_in[2];
    const float* Wv = (const float*)d_in[3];
    const float* Wo = (const float*)d_in[4];
    float* out = (float*)d_out;

    float *Qp, *Kp, *Vp, *Op;
    cudaGetSymbolAddress((void**)&Qp, g_Q);
    cudaGetSymbolAddress((void**)&Kp, g_K);
    cudaGetSymbolAddress((void**)&Vp, g_V);
    cudaGetSymbolAddress((void**)&Op, g_O);

    cudaFuncSetAttribute(gemm_tf32_kernel,
                         cudaFuncAttributeMaxDynamicSharedMemorySize, SMEM_GEMM);
    cudaFuncSetAttribute(attn_mma_kernel,
                         cudaFuncAttributeMaxDynamicSharedMemorySize, SMEM_ATTN);

    // 1. RoPE tables (needed by GEMM epilogues)
    {
        int total = Tt * (HDd / 2);
        rope_tables_kernel<<<(total + 255) / 256, 256>>>();
    }
    // 2. Q projection with fused RoPE
    gemm_tf32_kernel<<<dim3(QW / 128, NROW / 128), 256, SMEM_GEMM>>>(
        x, Wq, Wq, Qp, Qp, /*split_bx=*/QW / 128, /*rope_bx=*/QW / 128, QW, Dd);
    // 3. Fused K+V projection (K half gets RoPE), 256 CTAs
    gemm_tf32_kernel<<<dim3(2 * KW / 128, NROW / 128), 256, SMEM_GEMM>>>(
        x, Wk, Wv, Kp, Vp, /*split_bx=*/KW / 128, /*rope_bx=*/KW / 128, KW, Dd);
    // 4. Attention (TF32 tensor cores)
    attn_mma_kernel<<<dim3(Tt / 64, Bb * Hh), 128, SMEM_ATTN>>>();
    // 5. Output projection (no RoPE)
    gemm_tf32_kernel<<<dim3(Dd / 128, NROW / 128), 256, SMEM_GEMM>>>(
        Op, Wo, Wo, out, out, /*split_bx=*/Dd / 128, /*rope_bx=*/0, Dd, Dd);
}

// round 12
// speedup vs baseline: 1.0599x; 1.0599x over previous
#include <cuda_runtime.h>
#include <math.h>

#define Bb   2
#define Tt   2048
#define Dd   2048
#define Hh   16
#define KVh  4
#define HDd  128
#define REP  (Hh / KVh)
#define NROW (Bb * Tt)
#define QW   (Hh * HDd)    // 2048
#define KW   (KVh * HDd)   // 512

// ---- scratch (static device globals; no allocation) ----
__device__ float g_Q[(size_t)NROW * QW];
__device__ float g_K[(size_t)NROW * KW];
__device__ float g_V[(size_t)NROW * KW];
__device__ float g_O[(size_t)NROW * QW];
__device__ float g_cos[Tt * (HDd / 2)];
__device__ float g_sin[Tt * (HDd / 2)];

// ============================================================
// common PTX helpers
// ============================================================
__device__ __forceinline__ unsigned f2tf32(float x) {
    unsigned r;
    asm("cvt.rna.tf32.f32 %0, %1;" : "=r"(r) : "f"(x));
    return r;
}

__device__ __forceinline__ void ldm_x4(unsigned* a, const unsigned* p) {
    unsigned addr = (unsigned)__cvta_generic_to_shared(p);
    asm volatile("ldmatrix.sync.aligned.m8n8.x4.shared.b16 {%0,%1,%2,%3}, [%4];"
        : "=r"(a[0]), "=r"(a[1]), "=r"(a[2]), "=r"(a[3]) : "r"(addr));
}

__device__ __forceinline__ void mma_tf32(float* c, const unsigned* a,
                                         unsigned b0, unsigned b1) {
    asm volatile(
        "mma.sync.aligned.m16n8k8.row.col.f32.tf32.tf32.f32 "
        "{%0,%1,%2,%3}, {%4,%5,%6,%7}, {%8,%9}, {%0,%1,%2,%3};"
        : "+f"(c[0]), "+f"(c[1]), "+f"(c[2]), "+f"(c[3])
        : "r"(a[0]), "r"(a[1]), "r"(a[2]), "r"(a[3]), "r"(b0), "r"(b1));
}

// ============================================================
// RoPE tables (double precision)
// ============================================================
__global__ void rope_tables_kernel() {
    int idx = blockIdx.x * blockDim.x + threadIdx.x;
    if (idx >= Tt * (HDd / 2)) return;
    int i = idx % (HDd / 2);
    int t = idx / (HDd / 2);
    double inv = exp(-((double)(2 * i) / (double)HDd) * log(10000.0));
    double a = (double)t * inv;
    g_cos[idx] = (float)cos(a);
    g_sin[idx] = (float)sin(a);
}

// ============================================================
// TF32 tensor-core GEMM with optional dual-output region and
// fused-RoPE epilogue. (unchanged)
// ============================================================
#define BM 128
#define BN 128
#define BK 32
#define LDA 36
#define LDB 132
#define ASZ (BM * LDA)
#define BSZ (BK * LDB)
#define SMEM_GEMM ((2 * ASZ + 2 * BSZ) * 4)

__global__ __launch_bounds__(256, 2) void gemm_tf32_kernel(
    const float* __restrict__ A,
    const float* __restrict__ B0, const float* __restrict__ B1,
    float* __restrict__ C0, float* __restrict__ C1,
    int split_bx, int rope_bx, int N, int K)
{
    extern __shared__ unsigned smem_u[];
    unsigned* As = smem_u;
    unsigned* Bs = smem_u + 2 * ASZ;

    const int bxr = blockIdx.x, by = blockIdx.y;
    const float* Bm;
    float* C;
    int bx;
    if (bxr < split_bx) { Bm = B0; C = C0; bx = bxr; }
    else                { Bm = B1; C = C1; bx = bxr - split_bx; }
    const bool rope = (bxr < rope_bx);

    const int tid = threadIdx.x;
    const int warp = tid >> 5, lane = tid & 31;
    const int wm = warp & 3;
    const int wn = warp >> 2;

    const int ar = tid >> 3;
    const int ac = (tid & 7) << 2;
    const int br = tid >> 5;
    const int bc = (tid & 31) << 2;

    const float* Ag = A + (size_t)(by * BM) * K;
    const float* Bg = Bm + bx * BN;

    float acc[2][8][4];
#pragma unroll
    for (int mt = 0; mt < 2; mt++)
#pragma unroll
        for (int nt = 0; nt < 8; nt++)
#pragma unroll
            for (int i = 0; i < 4; i++) acc[mt][nt][i] = 0.f;

    float4 av[4], bv[4];

#pragma unroll
    for (int i = 0; i < 4; i++)
        av[i] = *(const float4*)(Ag + (size_t)(ar + 32 * i) * K + ac);
#pragma unroll
    for (int i = 0; i < 4; i++)
        bv[i] = *(const float4*)(Bg + (size_t)(br + 8 * i) * N + bc);
#pragma unroll
    for (int i = 0; i < 4; i++) {
        uint4 u;
        u.x = f2tf32(av[i].x); u.y = f2tf32(av[i].y);
        u.z = f2tf32(av[i].z); u.w = f2tf32(av[i].w);
        *(uint4*)&As[(ar + 32 * i) * LDA + ac] = u;
        uint4 w;
        w.x = f2tf32(bv[i].x); w.y = f2tf32(bv[i].y);
        w.z = f2tf32(bv[i].z); w.w = f2tf32(bv[i].w);
        *(uint4*)&Bs[(br + 8 * i) * LDB + bc] = w;
    }
    __syncthreads();

    int buf = 0;
    for (int k0 = BK; k0 <= K; k0 += BK) {
        if (k0 < K) {
#pragma unroll
            for (int i = 0; i < 4; i++)
                av[i] = *(const float4*)(Ag + (size_t)(ar + 32 * i) * K + k0 + ac);
#pragma unroll
            for (int i = 0; i < 4; i++)
                bv[i] = *(const float4*)(Bg + (size_t)(k0 + br + 8 * i) * N + bc);
        }

        const unsigned* Ab = As + buf * ASZ;
        const unsigned* Bt = Bs + buf * BSZ;
        const int arow = (lane & 7) + ((lane >> 3) & 1) * 8;
        const int acol = (lane >> 4) << 2;
#pragma unroll
        for (int ks = 0; ks < 4; ks++) {
            unsigned afr[2][4];
#pragma unroll
            for (int mt = 0; mt < 2; mt++) {
                int m0 = wm * 32 + mt * 16;
                ldm_x4(afr[mt], Ab + (m0 + arow) * LDA + ks * 8 + acol);
            }
            const unsigned* Bk = Bt + (ks * 8 + (lane & 3)) * LDB + wn * 64 + (lane >> 2);
#pragma unroll
            for (int nt = 0; nt < 8; nt++) {
                unsigned b0 = Bk[nt * 8];
                unsigned b1 = Bk[nt * 8 + 4 * LDB];
                mma_tf32(acc[0][nt], afr[0], b0, b1);
                mma_tf32(acc[1][nt], afr[1], b0, b1);
            }
        }

        if (k0 < K) {
            unsigned* Aw = As + (buf ^ 1) * ASZ;
            unsigned* Bw = Bs + (buf ^ 1) * BSZ;
#pragma unroll
            for (int i = 0; i < 4; i++) {
                uint4 u;
                u.x = f2tf32(av[i].x); u.y = f2tf32(av[i].y);
                u.z = f2tf32(av[i].z); u.w = f2tf32(av[i].w);
                *(uint4*)&Aw[(ar + 32 * i) * LDA + ac] = u;
                uint4 w;
                w.x = f2tf32(bv[i].x); w.y = f2tf32(bv[i].y);
                w.z = f2tf32(bv[i].z); w.w = f2tf32(bv[i].w);
                *(uint4*)&Bw[(br + 8 * i) * LDB + bc] = w;
            }
            __syncthreads();
            buf ^= 1;
        }
    }

    // ---- epilogue (optional fused RoPE) ----
    const int g = lane >> 2;
    const int cc = (lane & 3) << 1;
#pragma unroll
    for (int mt = 0; mt < 2; mt++) {
#pragma unroll
        for (int nt = 0; nt < 8; nt++) {
            int row = by * BM + wm * 32 + mt * 16 + g;
            int col = bx * BN + wn * 64 + nt * 8 + cc;
            if (rope) {
                int i = (col & (HDd - 1)) >> 1;
                int t0 = row & (Tt - 1);
                float c0 = g_cos[t0 * 64 + i], s0 = g_sin[t0 * 64 + i];
                float x1 = acc[mt][nt][0], x2 = acc[mt][nt][1];
                acc[mt][nt][0] = x1 * c0 - x2 * s0;
                acc[mt][nt][1] = x1 * s0 + x2 * c0;
                int t1 = (row + 8) & (Tt - 1);
                float c1 = g_cos[t1 * 64 + i], s1 = g_sin[t1 * 64 + i];
                x1 = acc[mt][nt][2]; x2 = acc[mt][nt][3];
                acc[mt][nt][2] = x1 * c1 - x2 * s1;
                acc[mt][nt][3] = x1 * s1 + x2 * c1;
            }
            *(float2*)&C[(size_t)row * N + col] =
                make_float2(acc[mt][nt][0], acc[mt][nt][1]);
            *(float2*)&C[(size_t)(row + 8) * N + col] =
                make_float2(acc[mt][nt][2], acc[mt][nt][3]);
        }
    }
}

// ============================================================
// TF32 tensor-core flash attention, causal, GQA.
// 128 threads = 4 warps; Q tile 64 rows (16/warp), KV tile 32.
// smem = 60416 B -> 3 CTAs/SM (12 warps/SM).
// Longest-first CTA order (qx reversed).
// ============================================================
#define KVT  32
#define LDQ  132
#define LDK  132
#define LDV  136
#define LDP  36
#define UNION_SZ (KVT * LDV)     // 4352 words (>= KVT*LDK = 4224)
#define SMEM_ATTN ((64 * LDQ + UNION_SZ + 64 * LDP) * 4)   // 60416 B

__global__ __launch_bounds__(128, 3) void attn_mma_kernel() {
    extern __shared__ unsigned smu[];
    unsigned* Qs = smu;
    unsigned* KV = Qs + 64 * LDQ;     // K tile OR V tile (union)
    unsigned* Ps = KV + UNION_SZ;

    const int bh = blockIdx.y;
    const int b = bh / Hh;
    const int h = bh % Hh;
    const int kvh = h / REP;
    const int qx = gridDim.x - 1 - blockIdx.x;   // longest-first
    const int q0 = qx * 64;
    const int tid = threadIdx.x, warp = tid >> 5, lane = tid & 31;
    const int g = lane >> 2, qd = lane & 3;
    const int arow = (lane & 7) + ((lane >> 3) & 1) * 8;
    const int acol = (lane >> 4) << 2;
    const float scale = 0.08838834764831845f; // 1/sqrt(128)

    // load Q tile (scale folded in, converted to tf32)
    const float* Qg = g_Q + ((size_t)(b * Tt + q0)) * QW + h * HDd;
    for (int x = tid; x < 64 * 32; x += 128) {
        int r = x >> 5, d4 = (x & 31) << 2;
        float4 q = *(const float4*)(Qg + (size_t)r * QW + d4);
        Qs[r * LDQ + d4 + 0] = f2tf32(q.x * scale);
        Qs[r * LDQ + d4 + 1] = f2tf32(q.y * scale);
        Qs[r * LDQ + d4 + 2] = f2tf32(q.z * scale);
        Qs[r * LDQ + d4 + 3] = f2tf32(q.w * scale);
    }

    float o[16][4];
#pragma unroll
    for (int nt = 0; nt < 16; nt++)
#pragma unroll
        for (int i = 0; i < 4; i++) o[nt][i] = 0.f;
    float m0 = -1e30f, m1 = -1e30f, l0 = 0.f, l1 = 0.f;

    const int ntiles = 2 * (qx + 1);     // 32-wide KV tiles covering j < q0+64
    for (int tile = 0; tile < ntiles; tile++) {
        const int j0 = tile * KVT;
        __syncthreads();   // prev V reads done (and Q stores on iter 0)

        // load K tile -> KV (row-major [j][d], tf32), 32 rows
        const float* Kg = g_K + ((size_t)(b * Tt + j0)) * KW + kvh * HDd;
        for (int x = tid; x < KVT * 32; x += 128) {
            int j = x >> 5, d4 = (x & 31) << 2;
            float4 kv = *(const float4*)(Kg + (size_t)j * KW + d4);
            KV[j * LDK + d4 + 0] = f2tf32(kv.x);
            KV[j * LDK + d4 + 1] = f2tf32(kv.y);
            KV[j * LDK + d4 + 2] = f2tf32(kv.z);
            KV[j * LDK + d4 + 3] = f2tf32(kv.w);
        }
        __syncthreads();

        // ---- S = (Q*scale) @ K^T : warp rows warp*16..+16, cols 0..31 ----
        float s[4][4];
#pragma unroll
        for (int nt = 0; nt < 4; nt++)
#pragma unroll
            for (int i = 0; i < 4; i++) s[nt][i] = 0.f;

#pragma unroll
        for (int ks = 0; ks < 16; ks++) {
            unsigned afr[4];
            ldm_x4(afr, Qs + (warp * 16 + arow) * LDQ + ks * 8 + acol);
#pragma unroll
            for (int ntp = 0; ntp < 2; ntp++) {
                unsigned bfr[4];
                ldm_x4(bfr, KV + (ntp * 16 + arow) * LDK + ks * 8 + acol);
                mma_tf32(s[2 * ntp],     afr, bfr[0], bfr[2]);
                mma_tf32(s[2 * ntp + 1], afr, bfr[1], bfr[3]);
            }
        }

        // causal mask (global compare; only last two tiles can mask)
        if (j0 + KVT - 1 > q0) {
            int r0 = q0 + warp * 16 + g, r1 = r0 + 8;
#pragma unroll
            for (int nt = 0; nt < 4; nt++) {
                int c = j0 + nt * 8 + 2 * qd;
                if (c > r0)     s[nt][0] = -1e30f;
                if (c + 1 > r0) s[nt][1] = -1e30f;
                if (c > r1)     s[nt][2] = -1e30f;
                if (c + 1 > r1) s[nt][3] = -1e30f;
            }
        }

        // ---- online softmax ----
        float mx0 = -1e30f, mx1 = -1e30f;
#pragma unroll
        for (int nt = 0; nt < 4; nt++) {
            mx0 = fmaxf(mx0, fmaxf(s[nt][0], s[nt][1]));
            mx1 = fmaxf(mx1, fmaxf(s[nt][2], s[nt][3]));
        }
        mx0 = fmaxf(mx0, __shfl_xor_sync(0xFFFFFFFFu, mx0, 1));
        mx0 = fmaxf(mx0, __shfl_xor_sync(0xFFFFFFFFu, mx0, 2));
        mx1 = fmaxf(mx1, __shfl_xor_sync(0xFFFFFFFFu, mx1, 1));
        mx1 = fmaxf(mx1, __shfl_xor_sync(0xFFFFFFFFu, mx1, 2));

        float mn0 = fmaxf(m0, mx0), mn1 = fmaxf(m1, mx1);
        float a0 = __expf(m0 - mn0), a1 = __expf(m1 - mn1);
        m0 = mn0; m1 = mn1;

        float ps0 = 0.f, ps1 = 0.f;
        unsigned* Pr0 = Ps + (warp * 16 + g) * LDP;
        unsigned* Pr1 = Pr0 + 8 * LDP;
#pragma unroll
        for (int nt = 0; nt < 4; nt++) {
            float p0 = __expf(s[nt][0] - mn0);
            float p1 = __expf(s[nt][1] - mn0);
            float p2 = __expf(s[nt][2] - mn1);
            float p3 = __expf(s[nt][3] - mn1);
            ps0 += p0 + p1; ps1 += p2 + p3;
            int c = nt * 8 + 2 * qd;
            *(uint2*)&Pr0[c] = make_uint2(f2tf32(p0), f2tf32(p1));
            *(uint2*)&Pr1[c] = make_uint2(f2tf32(p2), f2tf32(p3));
        }
        ps0 += __shfl_xor_sync(0xFFFFFFFFu, ps0, 1);
        ps0 += __shfl_xor_sync(0xFFFFFFFFu, ps0, 2);
        ps1 += __shfl_xor_sync(0xFFFFFFFFu, ps1, 1);
        ps1 += __shfl_xor_sync(0xFFFFFFFFu, ps1, 2);
        l0 = l0 * a0 + ps0;
        l1 = l1 * a1 + ps1;
#pragma unroll
        for (int nt = 0; nt < 16; nt++) {
            o[nt][0] *= a0; o[nt][1] *= a0;
            o[nt][2] *= a1; o[nt][3] *= a1;
        }

        __syncthreads();  // all warps done reading K; Ps visible

        // load V tile -> KV (row-major [j][d], stride LDV, tf32), 32 rows
        const float* Vg = g_V + ((size_t)(b * Tt + j0)) * KW + kvh * HDd;
        for (int x = tid; x < KVT * 32; x += 128) {
            int j = x >> 5, d4 = (x & 31) << 2;
            float4 vv = *(const float4*)(Vg + (size_t)j * KW + d4);
            KV[j * LDV + d4 + 0] = f2tf32(vv.x);
            KV[j * LDV + d4 + 1] = f2tf32(vv.y);
            KV[j * LDV + d4 + 2] = f2tf32(vv.z);
            KV[j * LDV + d4 + 3] = f2tf32(vv.w);
        }
        __syncthreads();

        // ---- O += P @ V  (scalar-LDS B operands; conflict-free) ----
#pragma unroll
        for (int ks = 0; ks < 4; ks++) {
            unsigned afr[4];
            ldm_x4(afr, Ps + (warp * 16 + arow) * LDP + ks * 8 + acol);
#pragma unroll
            for (int nt = 0; nt < 16; nt++) {
                unsigned b0 = KV[(ks * 8 + qd) * LDV + nt * 8 + g];
                unsigned b1 = KV[(ks * 8 + qd + 4) * LDV + nt * 8 + g];
                mma_tf32(o[nt], afr, b0, b1);
            }
        }
    }

    // ---- epilogue: normalize, store ----
    float i0 = 1.f / l0, i1 = 1.f / l1;
    float* Og = g_O + ((size_t)(b * Tt + q0 + warp * 16 + g)) * QW + h * HDd;
#pragma unroll
    for (int nt = 0; nt < 16; nt++) {
        int c = nt * 8 + 2 * qd;
        *(float2*)(Og + c) = make_float2(o[nt][0] * i0, o[nt][1] * i0);
        *(float2*)(Og + (size_t)8 * QW + c) = make_float2(o[nt][2] * i1, o[nt][3] * i1);
    }
}

// ============================================================
extern "C" void kernel_launch(void* const* d_in, const int* in_sizes, int n_in,
                              void* d_out, int out_size) {
    (void)in_sizes; (void)n_in; (void)out_size;
    const float* x  = (const float*)d_in[0];
    const float* Wq = (const float*)d_in[1];
    const float* Wk = (const float*)d_in[2];
    const float* Wv = (const float*)d_in[3];
    const float* Wo = (const float*)d_in[4];
    float* out = (float*)d_out;

    float *Qp, *Kp, *Vp, *Op;
    cudaGetSymbolAddress((void**)&Qp, g_Q);
    cudaGetSymbolAddress((void**)&Kp, g_K);
    cudaGetSymbolAddress((void**)&Vp, g_V);
    cudaGetSymbolAddress((void**)&Op, g_O);

    cudaFuncSetAttribute(gemm_tf32_kernel,
                         cudaFuncAttributeMaxDynamicSharedMemorySize, SMEM_GEMM);
    cudaFuncSetAttribute(attn_mma_kernel,
                         cudaFuncAttributeMaxDynamicSharedMemorySize, SMEM_ATTN);

    // 1. RoPE tables (needed by GEMM epilogues)
    {
        int total = Tt * (HDd / 2);
        rope_tables_kernel<<<(total + 255) / 256, 256>>>();
    }
    // 2. Q projection with fused RoPE
    gemm_tf32_kernel<<<dim3(QW / 128, NROW / 128), 256, SMEM_GEMM>>>(
        x, Wq, Wq, Qp, Qp, /*split_bx=*/QW / 128, /*rope_bx=*/QW / 128, QW, Dd);
    // 3. Fused K+V projection (K half gets RoPE), 256 CTAs
    gemm_tf32_kernel<<<dim3(2 * KW / 128, NROW / 128), 256, SMEM_GEMM>>>(
        x, Wk, Wv, Kp, Vp, /*split_bx=*/KW / 128, /*rope_bx=*/KW / 128, KW, Dd);
    // 4. Attention (TF32 tensor cores, 3 CTAs/SM)
    attn_mma_kernel<<<dim3(Tt / 64, Bb * Hh), 128, SMEM_ATTN>>>();
    // 5. Output projection (no RoPE)
    gemm_tf32_kernel<<<dim3(Dd / 128, NROW / 128), 256, SMEM_GEMM>>>(
        Op, Wo, Wo, out, out, /*split_bx=*/Dd / 128, /*rope_bx=*/0, Dd, Dd);
}

// round 13
// speedup vs baseline: 1.1264x; 1.0628x over previous
#include <cuda_runtime.h>
#include <math.h>

#define Bb   2
#define Tt   2048
#define Dd   2048
#define Hh   16
#define KVh  4
#define HDd  128
#define REP  (Hh / KVh)
#define NROW (Bb * Tt)
#define QW   (Hh * HDd)    // 2048
#define KW   (KVh * HDd)   // 512

// ---- scratch (static device globals; no allocation) ----
__device__ float g_Q[(size_t)NROW * QW];   // tf32-rounded, pre-scaled
__device__ float g_K[(size_t)NROW * KW];   // tf32-rounded
__device__ float g_V[(size_t)NROW * KW];   // tf32-rounded
__device__ float g_O[(size_t)NROW * QW];
__device__ float g_cos[Tt * (HDd / 2)];
__device__ float g_sin[Tt * (HDd / 2)];

// ============================================================
// common PTX helpers
// ============================================================
__device__ __forceinline__ unsigned f2tf32(float x) {
    unsigned r;
    asm("cvt.rna.tf32.f32 %0, %1;" : "=r"(r) : "f"(x));
    return r;
}

__device__ __forceinline__ void ldm_x4(unsigned* a, const unsigned* p) {
    unsigned addr = (unsigned)__cvta_generic_to_shared(p);
    asm volatile("ldmatrix.sync.aligned.m8n8.x4.shared.b16 {%0,%1,%2,%3}, [%4];"
        : "=r"(a[0]), "=r"(a[1]), "=r"(a[2]), "=r"(a[3]) : "r"(addr));
}

__device__ __forceinline__ void mma_tf32(float* c, const unsigned* a,
                                         unsigned b0, unsigned b1) {
    asm volatile(
        "mma.sync.aligned.m16n8k8.row.col.f32.tf32.tf32.f32 "
        "{%0,%1,%2,%3}, {%4,%5,%6,%7}, {%8,%9}, {%0,%1,%2,%3};"
        : "+f"(c[0]), "+f"(c[1]), "+f"(c[2]), "+f"(c[3])
        : "r"(a[0]), "r"(a[1]), "r"(a[2]), "r"(a[3]), "r"(b0), "r"(b1));
}

__device__ __forceinline__ void cp16(unsigned* s, const float* g) {
    unsigned a = (unsigned)__cvta_generic_to_shared(s);
    asm volatile("cp.async.cg.shared.global [%0], [%1], 16;" :: "r"(a), "l"(g));
}
#define CP_COMMIT() asm volatile("cp.async.commit_group;")
#define CP_WAIT0()  asm volatile("cp.async.wait_group 0;")
#define CP_WAIT1()  asm volatile("cp.async.wait_group 1;")

// ============================================================
// RoPE tables (double precision)
// ============================================================
__global__ void rope_tables_kernel() {
    int idx = blockIdx.x * blockDim.x + threadIdx.x;
    if (idx >= Tt * (HDd / 2)) return;
    int i = idx % (HDd / 2);
    int t = idx / (HDd / 2);
    double inv = exp(-((double)(2 * i) / (double)HDd) * log(10000.0));
    double a = (double)t * inv;
    g_cos[idx] = (float)cos(a);
    g_sin[idx] = (float)sin(a);
}

// ============================================================
// TF32 tensor-core GEMM, dual-output, fused-RoPE epilogue,
// optional output scaling + tf32 output rounding.
// ============================================================
#define BM 128
#define BN 128
#define BK 32
#define LDA 36
#define LDB 132
#define ASZ (BM * LDA)
#define BSZ (BK * LDB)
#define SMEM_GEMM ((2 * ASZ + 2 * BSZ) * 4)

__global__ __launch_bounds__(256, 2) void gemm_tf32_kernel(
    const float* __restrict__ A,
    const float* __restrict__ B0, const float* __restrict__ B1,
    float* __restrict__ C0, float* __restrict__ C1,
    int split_bx, int rope_bx, int N, int K,
    float oscale, int tf32_out)
{
    extern __shared__ unsigned smem_u[];
    unsigned* As = smem_u;
    unsigned* Bs = smem_u + 2 * ASZ;

    const int bxr = blockIdx.x, by = blockIdx.y;
    const float* Bm;
    float* C;
    int bx;
    if (bxr < split_bx) { Bm = B0; C = C0; bx = bxr; }
    else                { Bm = B1; C = C1; bx = bxr - split_bx; }
    const bool rope = (bxr < rope_bx);

    const int tid = threadIdx.x;
    const int warp = tid >> 5, lane = tid & 31;
    const int wm = warp & 3;
    const int wn = warp >> 2;

    const int ar = tid >> 3;
    const int ac = (tid & 7) << 2;
    const int br = tid >> 5;
    const int bc = (tid & 31) << 2;

    const float* Ag = A + (size_t)(by * BM) * K;
    const float* Bg = Bm + bx * BN;

    float acc[2][8][4];
#pragma unroll
    for (int mt = 0; mt < 2; mt++)
#pragma unroll
        for (int nt = 0; nt < 8; nt++)
#pragma unroll
            for (int i = 0; i < 4; i++) acc[mt][nt][i] = 0.f;

    float4 av[4], bv[4];

#pragma unroll
    for (int i = 0; i < 4; i++)
        av[i] = *(const float4*)(Ag + (size_t)(ar + 32 * i) * K + ac);
#pragma unroll
    for (int i = 0; i < 4; i++)
        bv[i] = *(const float4*)(Bg + (size_t)(br + 8 * i) * N + bc);
#pragma unroll
    for (int i = 0; i < 4; i++) {
        uint4 u;
        u.x = f2tf32(av[i].x); u.y = f2tf32(av[i].y);
        u.z = f2tf32(av[i].z); u.w = f2tf32(av[i].w);
        *(uint4*)&As[(ar + 32 * i) * LDA + ac] = u;
        uint4 w;
        w.x = f2tf32(bv[i].x); w.y = f2tf32(bv[i].y);
        w.z = f2tf32(bv[i].z); w.w = f2tf32(bv[i].w);
        *(uint4*)&Bs[(br + 8 * i) * LDB + bc] = w;
    }
    __syncthreads();

    int buf = 0;
    for (int k0 = BK; k0 <= K; k0 += BK) {
        if (k0 < K) {
#pragma unroll
            for (int i = 0; i < 4; i++)
                av[i] = *(const float4*)(Ag + (size_t)(ar + 32 * i) * K + k0 + ac);
#pragma unroll
            for (int i = 0; i < 4; i++)
                bv[i] = *(const float4*)(Bg + (size_t)(k0 + br + 8 * i) * N + bc);
        }

        const unsigned* Ab = As + buf * ASZ;
        const unsigned* Bt = Bs + buf * BSZ;
        const int arow = (lane & 7) + ((lane >> 3) & 1) * 8;
        const int acol = (lane >> 4) << 2;
#pragma unroll
        for (int ks = 0; ks < 4; ks++) {
            unsigned afr[2][4];
#pragma unroll
            for (int mt = 0; mt < 2; mt++) {
                int m0 = wm * 32 + mt * 16;
                ldm_x4(afr[mt], Ab + (m0 + arow) * LDA + ks * 8 + acol);
            }
            const unsigned* Bk = Bt + (ks * 8 + (lane & 3)) * LDB + wn * 64 + (lane >> 2);
#pragma unroll
            for (int nt = 0; nt < 8; nt++) {
                unsigned b0 = Bk[nt * 8];
                unsigned b1 = Bk[nt * 8 + 4 * LDB];
                mma_tf32(acc[0][nt], afr[0], b0, b1);
                mma_tf32(acc[1][nt], afr[1], b0, b1);
            }
        }

        if (k0 < K) {
            unsigned* Aw = As + (buf ^ 1) * ASZ;
            unsigned* Bw = Bs + (buf ^ 1) * BSZ;
#pragma unroll
            for (int i = 0; i < 4; i++) {
                uint4 u;
                u.x = f2tf32(av[i].x); u.y = f2tf32(av[i].y);
                u.z = f2tf32(av[i].z); u.w = f2tf32(av[i].w);
                *(uint4*)&Aw[(ar + 32 * i) * LDA + ac] = u;
                uint4 w;
                w.x = f2tf32(bv[i].x); w.y = f2tf32(bv[i].y);
                w.z = f2tf32(bv[i].z); w.w = f2tf32(bv[i].w);
                *(uint4*)&Bw[(br + 8 * i) * LDB + bc] = w;
            }
            __syncthreads();
            buf ^= 1;
        }
    }

    // ---- epilogue (optional fused RoPE + scale + tf32 rounding) ----
    const int g = lane >> 2;
    const int cc = (lane & 3) << 1;
#pragma unroll
    for (int mt = 0; mt < 2; mt++) {
#pragma unroll
        for (int nt = 0; nt < 8; nt++) {
            int row = by * BM + wm * 32 + mt * 16 + g;
            int col = bx * BN + wn * 64 + nt * 8 + cc;
            float v0 = acc[mt][nt][0], v1 = acc[mt][nt][1];
            float v2 = acc[mt][nt][2], v3 = acc[mt][nt][3];
            if (rope) {
                int i = (col & (HDd - 1)) >> 1;
                int t0 = row & (Tt - 1);
                float c0 = g_cos[t0 * 64 + i], s0 = g_sin[t0 * 64 + i];
                float x1 = v0, x2 = v1;
                v0 = x1 * c0 - x2 * s0;
                v1 = x1 * s0 + x2 * c0;
                int t1 = (row + 8) & (Tt - 1);
                float c1 = g_cos[t1 * 64 + i], s1 = g_sin[t1 * 64 + i];
                x1 = v2; x2 = v3;
                v2 = x1 * c1 - x2 * s1;
                v3 = x1 * s1 + x2 * c1;
            }
            v0 *= oscale; v1 *= oscale; v2 *= oscale; v3 *= oscale;
            if (tf32_out) {
                v0 = __uint_as_float(f2tf32(v0));
                v1 = __uint_as_float(f2tf32(v1));
                v2 = __uint_as_float(f2tf32(v2));
                v3 = __uint_as_float(f2tf32(v3));
            }
            *(float2*)&C[(size_t)row * N + col] = make_float2(v0, v1);
            *(float2*)&C[(size_t)(row + 8) * N + col] = make_float2(v2, v3);
        }
    }
}

// ============================================================
// TF32 tensor-core flash attention, causal, GQA.
// 128 threads = 4 warps; Q tile 64 rows (16/warp), KV tile 32.
// Inputs pre-rounded to tf32 (Q pre-scaled) -> all tile loads are
// cp.async 16B copies, software-pipelined:
//   V[i] copy hidden under QK^T, K[i+1] copy hidden under softmax+PV.
// smem: Qs 64x132 | Ks 32x132 | Vs 32x136 | Ps 64x36 = 77312 B
//   -> 3 CTAs/SM.
// ============================================================
#define KVT  32
#define LDQ  132
#define LDK  132
#define LDV  136
#define LDP  36
#define QS_W (64 * LDQ)     // 8448
#define KS_W (KVT * LDK)    // 4224
#define VS_W (KVT * LDV)    // 4352
#define SMEM_ATTN ((QS_W + KS_W + VS_W + 64 * LDP) * 4)   // 77312 B

__global__ __launch_bounds__(128, 3) void attn_mma_kernel() {
    extern __shared__ unsigned smu[];
    unsigned* Qs = smu;
    unsigned* Ks = Qs + QS_W;
    unsigned* Vs = Ks + KS_W;
    unsigned* Ps = Vs + VS_W;

    const int bh = blockIdx.y;
    const int b = bh / Hh;
    const int h = bh % Hh;
    const int kvh = h / REP;
    const int qx = gridDim.x - 1 - blockIdx.x;   // longest-first
    const int q0 = qx * 64;
    const int tid = threadIdx.x, warp = tid >> 5, lane = tid & 31;
    const int g = lane >> 2, qd = lane & 3;
    const int arow = (lane & 7) + ((lane >> 3) & 1) * 8;
    const int acol = (lane >> 4) << 2;

    const int cr = tid >> 2;            // copy row (0..31)
    const int cd = (tid & 3) << 3;      // copy col base for Q (2 chunks of 4)
    const float* Kbase = g_K + (size_t)b * Tt * KW + kvh * HDd;
    const float* Vbase = g_V + (size_t)b * Tt * KW + kvh * HDd;

    // ---- prologue: async-copy Q tile and K tile 0 (one group) ----
    {
        const float* Qg = g_Q + ((size_t)(b * Tt + q0)) * QW + h * HDd;
#pragma unroll
        for (int x = 0; x < 16; x++) {
            int r = (tid + x * 128) >> 5, d4 = ((tid + x * 128) & 31) << 2;
            cp16(&Qs[r * LDQ + d4], Qg + (size_t)r * QW + d4);
        }
        const float* Kg = Kbase;  // tile 0 (j0 = 0)
#pragma unroll
        for (int x = 0; x < 8; x++) {
            int j = (tid + x * 128) >> 5, d4 = ((tid + x * 128) & 31) << 2;
            cp16(&Ks[j * LDK + d4], Kg + (size_t)j * KW + d4);
        }
        CP_COMMIT();
    }

    float o[16][4];
#pragma unroll
    for (int nt = 0; nt < 16; nt++)
#pragma unroll
        for (int i = 0; i < 4; i++) o[nt][i] = 0.f;
    float m0 = -1e30f, m1 = -1e30f, l0 = 0.f, l1 = 0.f;

    const int ntiles = 2 * (qx + 1);
    for (int tile = 0; tile < ntiles; tile++) {
        const int j0 = tile * KVT;

        CP_WAIT0();          // K[tile] (+Q on tile 0) landed
        __syncthreads();     // K visible; V buffer free (all past prev PV)

        // issue V[tile] copy (hidden under QK^T)
        {
            const float* Vg = Vbase + (size_t)j0 * KW;
#pragma unroll
            for (int x = 0; x < 8; x++) {
                int j = (tid + x * 128) >> 5, d4 = ((tid + x * 128) & 31) << 2;
                cp16(&Vs[j * LDV + d4], Vg + (size_t)j * KW + d4);
            }
            CP_COMMIT();
        }

        // ---- S = Q @ K^T : warp rows warp*16..+16, cols 0..31 ----
        float s[4][4];
#pragma unroll
        for (int nt = 0; nt < 4; nt++)
#pragma unroll
            for (int i = 0; i < 4; i++) s[nt][i] = 0.f;

#pragma unroll
        for (int ks = 0; ks < 16; ks++) {
            unsigned afr[4];
            ldm_x4(afr, Qs + (warp * 16 + arow) * LDQ + ks * 8 + acol);
#pragma unroll
            for (int ntp = 0; ntp < 2; ntp++) {
                unsigned bfr[4];
                ldm_x4(bfr, Ks + (ntp * 16 + arow) * LDK + ks * 8 + acol);
                mma_tf32(s[2 * ntp],     afr, bfr[0], bfr[2]);
                mma_tf32(s[2 * ntp + 1], afr, bfr[1], bfr[3]);
            }
        }

        __syncthreads();     // all warps done reading Ks

        // issue K[tile+1] copy (clamped on last tile; hidden under softmax+PV)
        {
            int jn = (tile + 1 < ntiles) ? (j0 + KVT) : 0;
            const float* Kg = Kbase + (size_t)jn * KW;
#pragma unroll
            for (int x = 0; x < 8; x++) {
                int j = (tid + x * 128) >> 5, d4 = ((tid + x * 128) & 31) << 2;
                cp16(&Ks[j * LDK + d4], Kg + (size_t)j * KW + d4);
            }
            CP_COMMIT();
        }

        // causal mask (only tiles overlapping the diagonal)
        if (j0 + KVT - 1 > q0) {
            int r0 = q0 + warp * 16 + g, r1 = r0 + 8;
#pragma unroll
            for (int nt = 0; nt < 4; nt++) {
                int c = j0 + nt * 8 + 2 * qd;
                if (c > r0)     s[nt][0] = -1e30f;
                if (c + 1 > r0) s[nt][1] = -1e30f;
                if (c > r1)     s[nt][2] = -1e30f;
                if (c + 1 > r1) s[nt][3] = -1e30f;
            }
        }

        // ---- online softmax ----
        float mx0 = -1e30f, mx1 = -1e30f;
#pragma unroll
        for (int nt = 0; nt < 4; nt++) {
            mx0 = fmaxf(mx0, fmaxf(s[nt][0], s[nt][1]));
            mx1 = fmaxf(mx1, fmaxf(s[nt][2], s[nt][3]));
        }
        mx0 = fmaxf(mx0, __shfl_xor_sync(0xFFFFFFFFu, mx0, 1));
        mx0 = fmaxf(mx0, __shfl_xor_sync(0xFFFFFFFFu, mx0, 2));
        mx1 = fmaxf(mx1, __shfl_xor_sync(0xFFFFFFFFu, mx1, 1));
        mx1 = fmaxf(mx1, __shfl_xor_sync(0xFFFFFFFFu, mx1, 2));

        float mn0 = fmaxf(m0, mx0), mn1 = fmaxf(m1, mx1);
        float a0 = __expf(m0 - mn0), a1 = __expf(m1 - mn1);
        m0 = mn0; m1 = mn1;

        float ps0 = 0.f, ps1 = 0.f;
        unsigned* Pr0 = Ps + (warp * 16 + g) * LDP;
        unsigned* Pr1 = Pr0 + 8 * LDP;
#pragma unroll
        for (int nt = 0; nt < 4; nt++) {
            float p0 = __expf(s[nt][0] - mn0);
            float p1 = __expf(s[nt][1] - mn0);
            float p2 = __expf(s[nt][2] - mn1);
            float p3 = __expf(s[nt][3] - mn1);
            ps0 += p0 + p1; ps1 += p2 + p3;
            int c = nt * 8 + 2 * qd;
            *(uint2*)&Pr0[c] = make_uint2(f2tf32(p0), f2tf32(p1));
            *(uint2*)&Pr1[c] = make_uint2(f2tf32(p2), f2tf32(p3));
        }
        ps0 += __shfl_xor_sync(0xFFFFFFFFu, ps0, 1);
        ps0 += __shfl_xor_sync(0xFFFFFFFFu, ps0, 2);
        ps1 += __shfl_xor_sync(0xFFFFFFFFu, ps1, 1);
        ps1 += __shfl_xor_sync(0xFFFFFFFFu, ps1, 2);
        l0 = l0 * a0 + ps0;
        l1 = l1 * a1 + ps1;
#pragma unroll
        for (int nt = 0; nt < 16; nt++) {
            o[nt][0] *= a0; o[nt][1] *= a0;
            o[nt][2] *= a1; o[nt][3] *= a1;
        }

        CP_WAIT1();          // V[tile] landed (K[tile+1] may still fly)
        __syncthreads();     // V + Ps visible

        // ---- O += P @ V  (scalar-LDS B operands; conflict-free) ----
#pragma unroll
        for (int ks = 0; ks < 4; ks++) {
            unsigned afr[4];
            ldm_x4(afr, Ps + (warp * 16 + arow) * LDP + ks * 8 + acol);
#pragma unroll
            for (int nt = 0; nt < 16; nt++) {
                unsigned b0 = Vs[(ks * 8 + qd) * LDV + nt * 8 + g];
                unsigned b1 = Vs[(ks * 8 + qd + 4) * LDV + nt * 8 + g];
                mma_tf32(o[nt], afr, b0, b1);
            }
        }
    }
    CP_WAIT0();   // drain trailing prefetch before exit

    // ---- epilogue: normalize, store ----
    float i0 = 1.f / l0, i1 = 1.f / l1;
    float* Og = g_O + ((size_t)(b * Tt + q0 + warp * 16 + g)) * QW + h * HDd;
#pragma unroll
    for (int nt = 0; nt < 16; nt++) {
        int c = nt * 8 + 2 * qd;
        *(float2*)(Og + c) = make_float2(o[nt][0] * i0, o[nt][1] * i0);
        *(float2*)(Og + (size_t)8 * QW + c) = make_float2(o[nt][2] * i1, o[nt][3] * i1);
    }
}

// ============================================================
extern "C" void kernel_launch(void* const* d_in, const int* in_sizes, int n_in,
                              void* d_out, int out_size) {
    (void)in_sizes; (void)n_in; (void)out_size;
    const float* x  = (const float*)d_in[0];
    const float* Wq = (const float*)d_in[1];
    const float* Wk = (const float*)d_in[2];
    const float* Wv = (const float*)d_in[3];
    const float* Wo = (const float*)d_in[4];
    float* out = (float*)d_out;

    float *Qp, *Kp, *Vp, *Op;
    cudaGetSymbolAddress((void**)&Qp, g_Q);
    cudaGetSymbolAddress((void**)&Kp, g_K);
    cudaGetSymbolAddress((void**)&Vp, g_V);
    cudaGetSymbolAddress((void**)&Op, g_O);

    cudaFuncSetAttribute(gemm_tf32_kernel,
                         cudaFuncAttributeMaxDynamicSharedMemorySize, SMEM_GEMM);
    cudaFuncSetAttribute(attn_mma_kernel,
                         cudaFuncAttributeMaxDynamicSharedMemorySize, SMEM_ATTN);

    const float qscale = 0.08838834764831845f;   // 1/sqrt(128)

    // 1. RoPE tables (needed by GEMM epilogues)
    {
        int total = Tt * (HDd / 2);
        rope_tables_kernel<<<(total + 255) / 256, 256>>>();
    }
    // 2. Q projection: fused RoPE + scale + tf32 rounding
    gemm_tf32_kernel<<<dim3(QW / 128, NROW / 128), 256, SMEM_GEMM>>>(
        x, Wq, Wq, Qp, Qp, QW / 128, QW / 128, QW, Dd, qscale, 1);
    // 3. Fused K+V projection (K half RoPE'd), tf32 rounding, 256 CTAs
    gemm_tf32_kernel<<<dim3(2 * KW / 128, NROW / 128), 256, SMEM_GEMM>>>(
        x, Wk, Wv, Kp, Vp, KW / 128, KW / 128, KW, Dd, 1.0f, 1);
    // 4. Attention (TF32 tensor cores, cp.async pipelined, 3 CTAs/SM)
    attn_mma_kernel<<<dim3(Tt / 64, Bb * Hh), 128, SMEM_ATTN>>>();
    // 5. Output projection (plain fp32 out)
    gemm_tf32_kernel<<<dim3(Dd / 128, NROW / 128), 256, SMEM_GEMM>>>(
        Op, Wo, Wo, out, out, Dd / 128, 0, Dd, Dd, 1.0f, 0);
}

// round 14
// speedup vs baseline: 1.1564x; 1.0266x over previous
#include <cuda_runtime.h>
#include <math.h>

#define Bb   2
#define Tt   2048
#define Dd   2048
#define Hh   16
#define KVh  4
#define HDd  128
#define REP  (Hh / KVh)
#define NROW (Bb * Tt)
#define QW   (Hh * HDd)    // 2048
#define KW   (KVh * HDd)   // 512

// ---- scratch (static device globals; no allocation) ----
__device__ float g_Q[(size_t)NROW * QW];   // tf32-rounded, pre-scaled
__device__ float g_K[(size_t)NROW * KW];   // tf32-rounded
__device__ float g_V[(size_t)NROW * KW];   // tf32-rounded
__device__ float g_O[(size_t)NROW * QW];   // tf32-rounded (attn epilogue)
__device__ float g_xt[(size_t)NROW * Dd];  // tf32-rounded x
__device__ float g_Wqt[(size_t)Dd * QW];
__device__ float g_Wkt[(size_t)Dd * KW];
__device__ float g_Wvt[(size_t)Dd * KW];
__device__ float g_Wot[(size_t)QW * Dd];
__device__ float g_cos[Tt * (HDd / 2)];
__device__ float g_sin[Tt * (HDd / 2)];

// ============================================================
// common PTX helpers
// ============================================================
__device__ __forceinline__ unsigned f2tf32(float x) {
    unsigned r;
    asm("cvt.rna.tf32.f32 %0, %1;" : "=r"(r) : "f"(x));
    return r;
}

__device__ __forceinline__ void ldm_x4(unsigned* a, const unsigned* p) {
    unsigned addr = (unsigned)__cvta_generic_to_shared(p);
    asm volatile("ldmatrix.sync.aligned.m8n8.x4.shared.b16 {%0,%1,%2,%3}, [%4];"
        : "=r"(a[0]), "=r"(a[1]), "=r"(a[2]), "=r"(a[3]) : "r"(addr));
}

__device__ __forceinline__ void mma_tf32(float* c, const unsigned* a,
                                         unsigned b0, unsigned b1) {
    asm volatile(
        "mma.sync.aligned.m16n8k8.row.col.f32.tf32.tf32.f32 "
        "{%0,%1,%2,%3}, {%4,%5,%6,%7}, {%8,%9}, {%0,%1,%2,%3};"
        : "+f"(c[0]), "+f"(c[1]), "+f"(c[2]), "+f"(c[3])
        : "r"(a[0]), "r"(a[1]), "r"(a[2]), "r"(a[3]), "r"(b0), "r"(b1));
}

__device__ __forceinline__ void cp16(unsigned* s, const float* g) {
    unsigned a = (unsigned)__cvta_generic_to_shared(s);
    asm volatile("cp.async.cg.shared.global [%0], [%1], 16;" :: "r"(a), "l"(g));
}
#define CP_COMMIT() asm volatile("cp.async.commit_group;")
#define CP_WAIT0()  asm volatile("cp.async.wait_group 0;")
#define CP_WAIT1()  asm volatile("cp.async.wait_group 1;")

// ============================================================
// preround: dst = tf32_round(src), vectorized
// ============================================================
__global__ void preround_kernel(const float* __restrict__ src,
                                float* __restrict__ dst, int n4) {
    int i = blockIdx.x * blockDim.x + threadIdx.x;
    if (i >= n4) return;
    float4 v = ((const float4*)src)[i];
    uint4 u;
    u.x = f2tf32(v.x); u.y = f2tf32(v.y);
    u.z = f2tf32(v.z); u.w = f2tf32(v.w);
    ((uint4*)dst)[i] = u;
}

// ============================================================
// RoPE tables (double precision)
// ============================================================
__global__ void rope_tables_kernel() {
    int idx = blockIdx.x * blockDim.x + threadIdx.x;
    if (idx >= Tt * (HDd / 2)) return;
    int i = idx % (HDd / 2);
    int t = idx / (HDd / 2);
    double inv = exp(-((double)(2 * i) / (double)HDd) * log(10000.0));
    double a = (double)t * inv;
    g_cos[idx] = (float)cos(a);
    g_sin[idx] = (float)sin(a);
}

// ============================================================
// TF32 tensor-core GEMM, cp.async pipelined, dual-output,
// fused-RoPE epilogue + scale + optional tf32 output rounding.
// Inputs A,B MUST be pre-rounded to tf32 (no conversions inside).
// 128x128x32 tile, 256 threads, warp tile 32x64, 2-stage smem.
// ============================================================
#define BM 128
#define BN 128
#define BK 32
#define LDA 36
#define LDB 132
#define ASZ (BM * LDA)
#define BSZ (BK * LDB)
#define SMEM_GEMM ((2 * ASZ + 2 * BSZ) * 4)   // 70656 B

__global__ __launch_bounds__(256, 2) void gemm_tf32_kernel(
    const float* __restrict__ A,
    const float* __restrict__ B0, const float* __restrict__ B1,
    float* __restrict__ C0, float* __restrict__ C1,
    int split_bx, int rope_bx, int N, int K,
    float oscale, int tf32_out)
{
    extern __shared__ unsigned smem_u[];
    unsigned* As = smem_u;
    unsigned* Bs = smem_u + 2 * ASZ;

    const int bxr = blockIdx.x, by = blockIdx.y;
    const float* Bm;
    float* C;
    int bx;
    if (bxr < split_bx) { Bm = B0; C = C0; bx = bxr; }
    else                { Bm = B1; C = C1; bx = bxr - split_bx; }
    const bool rope = (bxr < rope_bx);

    const int tid = threadIdx.x;
    const int warp = tid >> 5, lane = tid & 31;
    const int wm = warp & 3;
    const int wn = warp >> 2;

    const float* Ag = A + (size_t)(by * BM) * K;
    const float* Bg = Bm + bx * BN;

    // cp.async chunk mappings: 4 A-chunks + 4 B-chunks per thread
    const int a_r = tid >> 3, a_c = (tid & 7) << 2;        // A: +32 rows/chunk
    const int b_r = tid >> 5, b_c = (tid & 31) << 2;       // B: +8 rows/chunk

    float acc[2][8][4];
#pragma unroll
    for (int mt = 0; mt < 2; mt++)
#pragma unroll
        for (int nt = 0; nt < 8; nt++)
#pragma unroll
            for (int i = 0; i < 4; i++) acc[mt][nt][i] = 0.f;

    // prologue: load tile 0
#pragma unroll
    for (int x = 0; x < 4; x++)
        cp16(&As[(a_r + 32 * x) * LDA + a_c], Ag + (size_t)(a_r + 32 * x) * K + a_c);
#pragma unroll
    for (int x = 0; x < 4; x++)
        cp16(&Bs[(b_r + 8 * x) * LDB + b_c], Bg + (size_t)(b_r + 8 * x) * N + b_c);
    CP_COMMIT();

    const int arow = (lane & 7) + ((lane >> 3) & 1) * 8;
    const int acol = (lane >> 4) << 2;

    int buf = 0;
    for (int k0 = 0; k0 < K; k0 += BK) {
        CP_WAIT0();
        __syncthreads();     // tile[buf] visible; all warps past compute[buf^1]

        if (k0 + BK < K) {   // issue tile k0+BK into buf^1 (overlaps compute)
            unsigned* Aw = As + (buf ^ 1) * ASZ;
            unsigned* Bw = Bs + (buf ^ 1) * BSZ;
#pragma unroll
            for (int x = 0; x < 4; x++)
                cp16(&Aw[(a_r + 32 * x) * LDA + a_c],
                     Ag + (size_t)(a_r + 32 * x) * K + k0 + BK + a_c);
#pragma unroll
            for (int x = 0; x < 4; x++)
                cp16(&Bw[(b_r + 8 * x) * LDB + b_c],
                     Bg + (size_t)(k0 + BK + b_r + 8 * x) * N + b_c);
            CP_COMMIT();
        }

        const unsigned* Ab = As + buf * ASZ;
        const unsigned* Bt = Bs + buf * BSZ;
#pragma unroll
        for (int ks = 0; ks < 4; ks++) {
            unsigned afr[2][4];
#pragma unroll
            for (int mt = 0; mt < 2; mt++) {
                int m0 = wm * 32 + mt * 16;
                ldm_x4(afr[mt], Ab + (m0 + arow) * LDA + ks * 8 + acol);
            }
            const unsigned* Bk = Bt + (ks * 8 + (lane & 3)) * LDB + wn * 64 + (lane >> 2);
#pragma unroll
            for (int nt = 0; nt < 8; nt++) {
                unsigned b0 = Bk[nt * 8];
                unsigned b1 = Bk[nt * 8 + 4 * LDB];
                mma_tf32(acc[0][nt], afr[0], b0, b1);
                mma_tf32(acc[1][nt], afr[1], b0, b1);
            }
        }
        buf ^= 1;
    }

    // ---- epilogue (optional fused RoPE + scale + tf32 rounding) ----
    const int g = lane >> 2;
    const int cc = (lane & 3) << 1;
#pragma unroll
    for (int mt = 0; mt < 2; mt++) {
#pragma unroll
        for (int nt = 0; nt < 8; nt++) {
            int row = by * BM + wm * 32 + mt * 16 + g;
            int col = bx * BN + wn * 64 + nt * 8 + cc;
            float v0 = acc[mt][nt][0], v1 = acc[mt][nt][1];
            float v2 = acc[mt][nt][2], v3 = acc[mt][nt][3];
            if (rope) {
                int i = (col & (HDd - 1)) >> 1;
                int t0 = row & (Tt - 1);
                float c0 = g_cos[t0 * 64 + i], s0 = g_sin[t0 * 64 + i];
                float x1 = v0, x2 = v1;
                v0 = x1 * c0 - x2 * s0;
                v1 = x1 * s0 + x2 * c0;
                int t1 = (row + 8) & (Tt - 1);
                float c1 = g_cos[t1 * 64 + i], s1 = g_sin[t1 * 64 + i];
                x1 = v2; x2 = v3;
                v2 = x1 * c1 - x2 * s1;
                v3 = x1 * s1 + x2 * c1;
            }
            v0 *= oscale; v1 *= oscale; v2 *= oscale; v3 *= oscale;
            if (tf32_out) {
                v0 = __uint_as_float(f2tf32(v0));
                v1 = __uint_as_float(f2tf32(v1));
                v2 = __uint_as_float(f2tf32(v2));
                v3 = __uint_as_float(f2tf32(v3));
            }
            *(float2*)&C[(size_t)row * N + col] = make_float2(v0, v1);
            *(float2*)&C[(size_t)(row + 8) * N + col] = make_float2(v2, v3);
        }
    }
}

// ============================================================
// TF32 tensor-core flash attention (unchanged from R13 except
// tf32-rounded output store), causal, GQA, cp.async pipelined.
// ============================================================
#define KVT  32
#define LDQ  132
#define LDK  132
#define LDV  136
#define LDP  36
#define QS_W (64 * LDQ)
#define KS_W (KVT * LDK)
#define VS_W (KVT * LDV)
#define SMEM_ATTN ((QS_W + KS_W + VS_W + 64 * LDP) * 4)   // 77312 B

__global__ __launch_bounds__(128, 3) void attn_mma_kernel() {
    extern __shared__ unsigned smu[];
    unsigned* Qs = smu;
    unsigned* Ks = Qs + QS_W;
    unsigned* Vs = Ks + KS_W;
    unsigned* Ps = Vs + VS_W;

    const int bh = blockIdx.y;
    const int b = bh / Hh;
    const int h = bh % Hh;
    const int kvh = h / REP;
    const int qx = gridDim.x - 1 - blockIdx.x;   // longest-first
    const int q0 = qx * 64;
    const int tid = threadIdx.x, warp = tid >> 5, lane = tid & 31;
    const int g = lane >> 2, qd = lane & 3;
    const int arow = (lane & 7) + ((lane >> 3) & 1) * 8;
    const int acol = (lane >> 4) << 2;

    const float* Kbase = g_K + (size_t)b * Tt * KW + kvh * HDd;
    const float* Vbase = g_V + (size_t)b * Tt * KW + kvh * HDd;

    // ---- prologue: async-copy Q tile and K tile 0 (one group) ----
    {
        const float* Qg = g_Q + ((size_t)(b * Tt + q0)) * QW + h * HDd;
#pragma unroll
        for (int x = 0; x < 16; x++) {
            int r = (tid + x * 128) >> 5, d4 = ((tid + x * 128) & 31) << 2;
            cp16(&Qs[r * LDQ + d4], Qg + (size_t)r * QW + d4);
        }
#pragma unroll
        for (int x = 0; x < 8; x++) {
            int j = (tid + x * 128) >> 5, d4 = ((tid + x * 128) & 31) << 2;
            cp16(&Ks[j * LDK + d4], Kbase + (size_t)j * KW + d4);
        }
        CP_COMMIT();
    }

    float o[16][4];
#pragma unroll
    for (int nt = 0; nt < 16; nt++)
#pragma unroll
        for (int i = 0; i < 4; i++) o[nt][i] = 0.f;
    float m0 = -1e30f, m1 = -1e30f, l0 = 0.f, l1 = 0.f;

    const int ntiles = 2 * (qx + 1);
    for (int tile = 0; tile < ntiles; tile++) {
        const int j0 = tile * KVT;

        CP_WAIT0();
        __syncthreads();

        // issue V[tile] copy (hidden under QK^T)
        {
            const float* Vg = Vbase + (size_t)j0 * KW;
#pragma unroll
            for (int x = 0; x < 8; x++) {
                int j = (tid + x * 128) >> 5, d4 = ((tid + x * 128) & 31) << 2;
                cp16(&Vs[j * LDV + d4], Vg + (size_t)j * KW + d4);
            }
            CP_COMMIT();
        }

        // ---- S = Q @ K^T ----
        float s[4][4];
#pragma unroll
        for (int nt = 0; nt < 4; nt++)
#pragma unroll
            for (int i = 0; i < 4; i++) s[nt][i] = 0.f;

#pragma unroll
        for (int ks = 0; ks < 16; ks++) {
            unsigned afr[4];
            ldm_x4(afr, Qs + (warp * 16 + arow) * LDQ + ks * 8 + acol);
#pragma unroll
            for (int ntp = 0; ntp < 2; ntp++) {
                unsigned bfr[4];
                ldm_x4(bfr, Ks + (ntp * 16 + arow) * LDK + ks * 8 + acol);
                mma_tf32(s[2 * ntp],     afr, bfr[0], bfr[2]);
                mma_tf32(s[2 * ntp + 1], afr, bfr[1], bfr[3]);
            }
        }

        __syncthreads();     // all warps done reading Ks

        // issue K[tile+1] copy (clamped; hidden under softmax+PV)
        {
            int jn = (tile + 1 < ntiles) ? (j0 + KVT) : 0;
            const float* Kg = Kbase + (size_t)jn * KW;
#pragma unroll
            for (int x = 0; x < 8; x++) {
                int j = (tid + x * 128) >> 5, d4 = ((tid + x * 128) & 31) << 2;
                cp16(&Ks[j * LDK + d4], Kg + (size_t)j * KW + d4);
            }
            CP_COMMIT();
        }

        // causal mask
        if (j0 + KVT - 1 > q0) {
            int r0 = q0 + warp * 16 + g, r1 = r0 + 8;
#pragma unroll
            for (int nt = 0; nt < 4; nt++) {
                int c = j0 + nt * 8 + 2 * qd;
                if (c > r0)     s[nt][0] = -1e30f;
                if (c + 1 > r0) s[nt][1] = -1e30f;
                if (c > r1)     s[nt][2] = -1e30f;
                if (c + 1 > r1) s[nt][3] = -1e30f;
            }
        }

        // ---- online softmax ----
        float mx0 = -1e30f, mx1 = -1e30f;
#pragma unroll
        for (int nt = 0; nt < 4; nt++) {
            mx0 = fmaxf(mx0, fmaxf(s[nt][0], s[nt][1]));
            mx1 = fmaxf(mx1, fmaxf(s[nt][2], s[nt][3]));
        }
        mx0 = fmaxf(mx0, __shfl_xor_sync(0xFFFFFFFFu, mx0, 1));
        mx0 = fmaxf(mx0, __shfl_xor_sync(0xFFFFFFFFu, mx0, 2));
        mx1 = fmaxf(mx1, __shfl_xor_sync(0xFFFFFFFFu, mx1, 1));
        mx1 = fmaxf(mx1, __shfl_xor_sync(0xFFFFFFFFu, mx1, 2));

        float mn0 = fmaxf(m0, mx0), mn1 = fmaxf(m1, mx1);
        float a0 = __expf(m0 - mn0), a1 = __expf(m1 - mn1);
        m0 = mn0; m1 = mn1;

        float ps0 = 0.f, ps1 = 0.f;
        unsigned* Pr0 = Ps + (warp * 16 + g) * LDP;
        unsigned* Pr1 = Pr0 + 8 * LDP;
#pragma unroll
        for (int nt = 0; nt < 4; nt++) {
            float p0 = __expf(s[nt][0] - mn0);
            float p1 = __expf(s[nt][1] - mn0);
            float p2 = __expf(s[nt][2] - mn1);
            float p3 = __expf(s[nt][3] - mn1);
            ps0 += p0 + p1; ps1 += p2 + p3;
            int c = nt * 8 + 2 * qd;
            *(uint2*)&Pr0[c] = make_uint2(f2tf32(p0), f2tf32(p1));
            *(uint2*)&Pr1[c] = make_uint2(f2tf32(p2), f2tf32(p3));
        }
        ps0 += __shfl_xor_sync(0xFFFFFFFFu, ps0, 1);
        ps0 += __shfl_xor_sync(0xFFFFFFFFu, ps0, 2);
        ps1 += __shfl_xor_sync(0xFFFFFFFFu, ps1, 1);
        ps1 += __shfl_xor_sync(0xFFFFFFFFu, ps1, 2);
        l0 = l0 * a0 + ps0;
        l1 = l1 * a1 + ps1;
#pragma unroll
        for (int nt = 0; nt < 16; nt++) {
            o[nt][0] *= a0; o[nt][1] *= a0;
            o[nt][2] *= a1; o[nt][3] *= a1;
        }

        CP_WAIT1();          // V[tile] landed
        __syncthreads();     // V + Ps visible

        // ---- O += P @ V ----
#pragma unroll
        for (int ks = 0; ks < 4; ks++) {
            unsigned afr[4];
            ldm_x4(afr, Ps + (warp * 16 + arow) * LDP + ks * 8 + acol);
#pragma unroll
            for (int nt = 0; nt < 16; nt++) {
                unsigned b0 = Vs[(ks * 8 + qd) * LDV + nt * 8 + g];
                unsigned b1 = Vs[(ks * 8 + qd + 4) * LDV + nt * 8 + g];
                mma_tf32(o[nt], afr, b0, b1);
            }
        }
    }
    CP_WAIT0();   // drain trailing prefetch

    // ---- epilogue: normalize, round to tf32, store ----
    float i0 = 1.f / l0, i1 = 1.f / l1;
    float* Og = g_O + ((size_t)(b * Tt + q0 + warp * 16 + g)) * QW + h * HDd;
#pragma unroll
    for (int nt = 0; nt < 16; nt++) {
        int c = nt * 8 + 2 * qd;
        float2 v0 = make_float2(__uint_as_float(f2tf32(o[nt][0] * i0)),
                                __uint_as_float(f2tf32(o[nt][1] * i0)));
        float2 v1 = make_float2(__uint_as_float(f2tf32(o[nt][2] * i1)),
                                __uint_as_float(f2tf32(o[nt][3] * i1)));
        *(float2*)(Og + c) = v0;
        *(float2*)(Og + (size_t)8 * QW + c) = v1;
    }
}

// ============================================================
extern "C" void kernel_launch(void* const* d_in, const int* in_sizes, int n_in,
                              void* d_out, int out_size) {
    (void)in_sizes; (void)n_in; (void)out_size;
    const float* x  = (const float*)d_in[0];
    const float* Wq = (const float*)d_in[1];
    const float* Wk = (const float*)d_in[2];
    const float* Wv = (const float*)d_in[3];
    const float* Wo = (const float*)d_in[4];
    float* out = (float*)d_out;

    float *Qp, *Kp, *Vp, *Op, *xt, *wqt, *wkt, *wvt, *wot;
    cudaGetSymbolAddress((void**)&Qp, g_Q);
    cudaGetSymbolAddress((void**)&Kp, g_K);
    cudaGetSymbolAddress((void**)&Vp, g_V);
    cudaGetSymbolAddress((void**)&Op, g_O);
    cudaGetSymbolAddress((void**)&xt, g_xt);
    cudaGetSymbolAddress((void**)&wqt, g_Wqt);
    cudaGetSymbolAddress((void**)&wkt, g_Wkt);
    cudaGetSymbolAddress((void**)&wvt, g_Wvt);
    cudaGetSymbolAddress((void**)&wot, g_Wot);

    cudaFuncSetAttribute(gemm_tf32_kernel,
                         cudaFuncAttributeMaxDynamicSharedMemorySize, SMEM_GEMM);
    cudaFuncSetAttribute(attn_mma_kernel,
                         cudaFuncAttributeMaxDynamicSharedMemorySize, SMEM_ATTN);

    const float qscale = 0.08838834764831845f;   // 1/sqrt(128)

    // 1. RoPE tables + preround inputs/weights to tf32
    {
        int total = Tt * (HDd / 2);
        rope_tables_kernel<<<(total + 255) / 256, 256>>>();
        int n;
        n = NROW * Dd / 4;  preround_kernel<<<(n + 255) / 256, 256>>>(x,  xt,  n);
        n = Dd * QW / 4;    preround_kernel<<<(n + 255) / 256, 256>>>(Wq, wqt, n);
        n = Dd * KW / 4;    preround_kernel<<<(n + 255) / 256, 256>>>(Wk, wkt, n);
        n = Dd * KW / 4;    preround_kernel<<<(n + 255) / 256, 256>>>(Wv, wvt, n);
        n = QW * Dd / 4;    preround_kernel<<<(n + 255) / 256, 256>>>(Wo, wot, n);
    }
    // 2. Q projection: fused RoPE + scale + tf32 rounding
    gemm_tf32_kernel<<<dim3(QW / 128, NROW / 128), 256, SMEM_GEMM>>>(
        xt, wqt, wqt, Qp, Qp, QW / 128, QW / 128, QW, Dd, qscale, 1);
    // 3. Fused K+V projection (K half RoPE'd), tf32 rounding
    gemm_tf32_kernel<<<dim3(2 * KW / 128, NROW / 128), 256, SMEM_GEMM>>>(
        xt, wkt, wvt, Kp, Vp, KW / 128, KW / 128, KW, Dd, 1.0f, 1);
    // 4. Attention (writes tf32-rounded O)
    attn_mma_kernel<<<dim3(Tt / 64, Bb * Hh), 128, SMEM_ATTN>>>();
    // 5. Output projection (plain fp32 out)
    gemm_tf32_kernel<<<dim3(Dd / 128, NROW / 128), 256, SMEM_GEMM>>>(
        Op, wot, wot, out, out, Dd / 128, 0, Dd, Dd, 1.0f, 0);
}